// round 3
// baseline (speedup 1.0000x reference)
#include <cuda_runtime.h>
#include <cuda_bf16.h>
#include <cstdint>

#define N_NODES 100000
#define N_EDGES 1600000
#define DFEAT   32

// Scratch aggregation buffer (12.8 MB) — __device__ global, no allocation.
__device__ float g_agg[(size_t)N_NODES * DFEAT];

// ---------------------------------------------------------------------------
// Kernel 1: zero the aggregation buffer (float4 stores).
// ---------------------------------------------------------------------------
__global__ void gine_zero_kernel() {
    const int n4 = N_NODES * DFEAT / 4;  // 800000 float4
    int i = blockIdx.x * blockDim.x + threadIdx.x;
    if (i < n4) {
        reinterpret_cast<float4*>(g_agg)[i] = make_float4(0.f, 0.f, 0.f, 0.f);
    }
}

// ---------------------------------------------------------------------------
// Kernel 2: edge phase. One thread per float4 chunk (8 threads per edge).
//   msg = relu(x[src] + e); red.global.add.v4.f32 into g_agg[dst].
// ---------------------------------------------------------------------------
__global__ void gine_edge_kernel(const float* __restrict__ node_inputs,
                                 const float* __restrict__ edge_inputs,
                                 const int*   __restrict__ src,
                                 const int*   __restrict__ dst) {
    long long idx = (long long)blockIdx.x * blockDim.x + threadIdx.x;
    const long long total = (long long)N_EDGES * (DFEAT / 4);  // 12.8M
    if (idx >= total) return;

    int e = (int)(idx >> 3);   // edge id
    int c = (int)(idx & 7);    // float4 chunk within the 32-float row

    int s = __ldg(&src[e]);
    int d = __ldg(&dst[e]);

    const float4* ep = reinterpret_cast<const float4*>(edge_inputs);
    const float4* np = reinterpret_cast<const float4*>(node_inputs);

    float4 ev = ep[(size_t)e * 8 + c];
    float4 xv = np[(size_t)s * 8 + c];

    float4 m;
    m.x = fmaxf(xv.x + ev.x, 0.f);
    m.y = fmaxf(xv.y + ev.y, 0.f);
    m.z = fmaxf(xv.z + ev.z, 0.f);
    m.w = fmaxf(xv.w + ev.w, 0.f);

    float* ap = g_agg + (size_t)d * DFEAT + c * 4;
    asm volatile("red.global.add.v4.f32 [%0], {%1, %2, %3, %4};"
                 :: "l"(ap), "f"(m.x), "f"(m.y), "f"(m.z), "f"(m.w)
                 : "memory");
}

// ---------------------------------------------------------------------------
// Kernel 3: node phase. Warp per node; lane o = output feature.
//   h[k] held by lane k, broadcast via shfl; W row per lane in registers.
//   out[n][o] = b[o] + sum_k ((1+eps)*x[n][k] + agg[n][k]) * W[o][k]
// ---------------------------------------------------------------------------
__global__ void gine_node_kernel(const float* __restrict__ node_inputs,
                                 const float* __restrict__ W,
                                 const float* __restrict__ b,
                                 const float* __restrict__ eps,
                                 float*       __restrict__ out) {
    int gtid   = blockIdx.x * blockDim.x + threadIdx.x;
    int warp   = gtid >> 5;
    int lane   = threadIdx.x & 31;
    int nwarps = (gridDim.x * blockDim.x) >> 5;

    // Each lane o caches W[o][0..31] in registers (L1-hit after first block).
    float w[32];
#pragma unroll
    for (int k = 0; k < 32; k++) w[k] = __ldg(&W[lane * 32 + k]);
    float bias = __ldg(&b[lane]);
    float ep1  = 1.0f + __ldg(&eps[0]);

    for (int n = warp; n < N_NODES; n += nwarps) {
        float h = ep1 * node_inputs[(size_t)n * 32 + lane]
                + g_agg[(size_t)n * 32 + lane];

        // 4 partial accumulators to break the FMA dependency chain.
        float a0 = bias, a1 = 0.f, a2 = 0.f, a3 = 0.f;
#pragma unroll
        for (int k = 0; k < 32; k += 4) {
            a0 = fmaf(__shfl_sync(0xffffffffu, h, k + 0), w[k + 0], a0);
            a1 = fmaf(__shfl_sync(0xffffffffu, h, k + 1), w[k + 1], a1);
            a2 = fmaf(__shfl_sync(0xffffffffu, h, k + 2), w[k + 2], a2);
            a3 = fmaf(__shfl_sync(0xffffffffu, h, k + 3), w[k + 3], a3);
        }
        out[(size_t)n * 32 + lane] = (a0 + a1) + (a2 + a3);
    }
}

// ---------------------------------------------------------------------------
// Launch: zero -> edges -> nodes, all on the capture stream (serialized).
// Input order per metadata: node_inputs, edge_inputs, src, dst, W, b, eps.
// ---------------------------------------------------------------------------
extern "C" void kernel_launch(void* const* d_in, const int* in_sizes, int n_in,
                              void* d_out, int out_size) {
    const float* node_inputs = (const float*)d_in[0];
    const float* edge_inputs = (const float*)d_in[1];
    const int*   src         = (const int*)  d_in[2];
    const int*   dst         = (const int*)  d_in[3];
    const float* W           = (const float*)d_in[4];
    const float* b           = (const float*)d_in[5];
    const float* eps         = (const float*)d_in[6];
    float*       out         = (float*)      d_out;

    // 1) zero agg: 800000 float4
    {
        int threads = 256;
        int blocks  = (N_NODES * DFEAT / 4 + threads - 1) / threads;
        gine_zero_kernel<<<blocks, threads>>>();
    }
    // 2) edge scatter: 12.8M threads
    {
        int threads = 256;
        long long total = (long long)N_EDGES * (DFEAT / 4);
        int blocks = (int)((total + threads - 1) / threads);
        gine_edge_kernel<<<blocks, threads>>>(node_inputs, edge_inputs, src, dst);
    }
    // 3) node linear: warp per node
    {
        int threads = 256;                // 8 warps/block
        int blocks  = 2048;               // 16384 warps, grid-stride over nodes
        gine_node_kernel<<<blocks, threads>>>(node_inputs, W, b, eps, out);
    }
}